// round 5
// baseline (speedup 1.0000x reference)
#include <cuda_runtime.h>

// CrossAttention collapses: K/V are one visual_features vector broadcast over
// all T keys, softmax over identical logits is uniform, so y == v everywhere:
//   out[b,t,:] = ((vf[b] @ Wv + bv) @ Wp + bp)   broadcast over t.
// x / Wq / bq / Wk / bk are mathematically dead.
//
// R3: split-K projections (63->15us). R4: bcast was issue/latency-bound
// (1 dependent LDG+STG per thread); now each thread loads r once and issues
// 8 independent STG.128 to consecutive t rows.

#define CDIM  1024
#define BDIM  4
#define TDIM  1024
#define KS    32              // split-K chunk count
#define ROWS  (CDIM / KS)     // 32 reduction rows per chunk
#define JT    128             // threads per proj block
#define JSPAN (JT * 4)        // 512 output columns per block (float4/thread)
#define JBLK  (CDIM / JSPAN)  // 2
#define TT    8               // t-rows stored per bcast thread

__device__ float g_pvv[KS][BDIM][CDIM];  // partials of vf @ Wv
__device__ float g_pr [KS][BDIM][CDIM];  // partials of vv @ Wp
__device__ float g_r  [BDIM][CDIM];      // final row to broadcast

// ---------------------------------------------------------------------------
// L1: partial[k][b][j0..j0+3] = sum_{i in chunk k} vf[b,i] * Wv[i,j]
__global__ __launch_bounds__(JT) void vv_partial_kernel(
    const float* __restrict__ vf, const float* __restrict__ Wv)
{
    const int jx = blockIdx.x, b = blockIdx.y, k = blockIdx.z;
    const int j0 = jx * JSPAN + threadIdx.x * 4;

    __shared__ float s_in[ROWS];
    if (threadIdx.x < ROWS)
        s_in[threadIdx.x] = vf[b * CDIM + k * ROWS + threadIdx.x];
    __syncthreads();

    float4 acc = make_float4(0.f, 0.f, 0.f, 0.f);
    #pragma unroll
    for (int i = 0; i < ROWS; ++i) {
        const float4 w = __ldg((const float4*)&Wv[(k * ROWS + i) * CDIM + j0]);
        const float s = s_in[i];
        acc.x += s * w.x; acc.y += s * w.y; acc.z += s * w.z; acc.w += s * w.w;
    }
    *(float4*)&g_pvv[k][b][j0] = acc;
}

// ---------------------------------------------------------------------------
// L2: reduce the needed vv slice (32 values x 32 partials + bv) in shared,
// then compute partials of vv @ Wp.
__global__ __launch_bounds__(JT) void r_partial_kernel(
    const float* __restrict__ bv, const float* __restrict__ Wp)
{
    const int jx = blockIdx.x, b = blockIdx.y, k = blockIdx.z;
    const int j0 = jx * JSPAN + threadIdx.x * 4;

    __shared__ float s_red[4][ROWS];
    __shared__ float s_in[ROWS];

    {
        const int i  = threadIdx.x & 31;
        const int kg = threadIdx.x >> 5;
        float s = 0.f;
        #pragma unroll
        for (int kk = kg * 8; kk < kg * 8 + 8; ++kk)
            s += g_pvv[kk][b][k * ROWS + i];
        s_red[kg][i] = s;
    }
    __syncthreads();
    if (threadIdx.x < ROWS)
        s_in[threadIdx.x] = s_red[0][threadIdx.x] + s_red[1][threadIdx.x]
                          + s_red[2][threadIdx.x] + s_red[3][threadIdx.x]
                          + bv[k * ROWS + threadIdx.x];
    __syncthreads();

    float4 acc = make_float4(0.f, 0.f, 0.f, 0.f);
    #pragma unroll
    for (int i = 0; i < ROWS; ++i) {
        const float4 w = __ldg((const float4*)&Wp[(k * ROWS + i) * CDIM + j0]);
        const float s = s_in[i];
        acc.x += s * w.x; acc.y += s * w.y; acc.z += s * w.z; acc.w += s * w.w;
    }
    *(float4*)&g_pr[k][b][j0] = acc;
}

// ---------------------------------------------------------------------------
// L3: g_r[b][j] = bp[j] + sum_k g_pr[k][b][j]. 4096 outputs, trivial.
__global__ __launch_bounds__(512) void r_reduce_kernel(const float* __restrict__ bp)
{
    const int idx = blockIdx.x * 512 + threadIdx.x;   // 0..4095
    const int b = idx >> 10;
    const int j = idx & (CDIM - 1);
    float s = bp[j];
    #pragma unroll
    for (int k = 0; k < KS; ++k)
        s += g_pr[k][b][j];
    g_r[b][j] = s;
}

// ---------------------------------------------------------------------------
// L4: out[b,t,:] = g_r[b,:]. Each thread owns one float4 column, loads it
// once, and stores it to TT consecutive t rows — 8 independent STG.128.
// Grid (TDIM/TT, BDIM) = (128, 4), 256 threads.
__global__ __launch_bounds__(256) void bcast_kernel(float4* __restrict__ out)
{
    const int c4 = threadIdx.x;            // 0..255 (CDIM/4)
    const int b  = blockIdx.y;
    const int t0 = blockIdx.x * TT;

    const float4 v = *(const float4*)&g_r[b][c4 * 4];
    float4* __restrict__ p = out + (size_t)(b * TDIM + t0) * (CDIM / 4) + c4;
    #pragma unroll
    for (int t = 0; t < TT; ++t)
        p[t * (CDIM / 4)] = v;
}

extern "C" void kernel_launch(void* const* d_in, const int* in_sizes, int n_in,
                              void* d_out, int out_size)
{
    (void)in_sizes; (void)n_in; (void)out_size;
    const float* vf = (const float*)d_in[1];
    const float* Wv = (const float*)d_in[6];
    const float* bv = (const float*)d_in[7];
    const float* Wp = (const float*)d_in[8];
    const float* bp = (const float*)d_in[9];

    dim3 pgrid(JBLK, BDIM, KS);                       // 2 x 4 x 32 = 256 blocks
    vv_partial_kernel<<<pgrid, JT>>>(vf, Wv);
    r_partial_kernel <<<pgrid, JT>>>(bv, Wp);
    r_reduce_kernel  <<<BDIM * CDIM / 512, 512>>>(bp);

    dim3 bgrid(TDIM / TT, BDIM);                      // 128 x 4 = 512 blocks
    bcast_kernel<<<bgrid, 256>>>((float4*)d_out);
}